// round 3
// baseline (speedup 1.0000x reference)
#include <cuda_runtime.h>
#include <cstdint>

#define N_   32
#define C_   256
#define O_   256
#define HW_  56
#define PIX  3136          // 56*56
#define CNTS 802816.0f     // 256*56*56 per-sample element count
#define EPSF 1e-5f

// ---------------- device scratch (no allocations allowed) ----------------
__device__ float    g_asum[N_];
__device__ float    g_m[O_];
__device__ __align__(16) unsigned g_wbits[O_ * 72];      // [o][tap][word] 9 taps * 8 words
__device__ int      g_pw[O_ * 9];                        // popc of wbits per (o,tap)
__device__ __align__(16) unsigned g_xbits[(size_t)N_ * PIX * 8]; // [n][pix][word]
__device__ int      g_xz_count;
__device__ int      g_wz_count;
__device__ int      g_xz_list[4096];                     // linear idx into x
__device__ int      g_wz_list[64];                       // linear idx into w

__device__ __forceinline__ float alpha_of(int n) {
    return fmaxf(2.f * g_asum[n] / CNTS, EPSF);
}

// ---------------- K0: zero counters/accumulators ----------------
__global__ void k_zero() {
    int t = blockIdx.x * blockDim.x + threadIdx.x;
    if (t < N_) g_asum[t] = 0.f;
    if (t < O_ * 9) g_pw[t] = 0;
    if (t == 0) { g_xz_count = 0; g_wz_count = 0; }
}

// ---------------- K1: pack x sign bits + accumulate sum|x| ----------------
// thread <-> pixel; loops all 256 channels; dense uint4 writes (no amplification)
// grid = 32 n * 13 chunks = 416 blocks, 256 threads
__global__ void k_packx(const float* __restrict__ x) {
    int b    = blockIdx.x;
    int n    = b & 31;
    int pix  = (b >> 5) * 256 + threadIdx.x;
    int tid  = threadIdx.x;

    unsigned bits[8] = {0,0,0,0,0,0,0,0};
    float s0 = 0.f, s1 = 0.f, s2 = 0.f, s3 = 0.f;

    if (pix < PIX) {
        const float* base = x + (size_t)n * C_ * PIX + pix;
#pragma unroll
        for (int w8 = 0; w8 < 8; w8++) {
            unsigned bb = 0;
#pragma unroll
            for (int c2 = 0; c2 < 32; c2++) {
                float v = base[(size_t)(w8 * 32 + c2) * PIX];
                float a = fabsf(v);
                if ((c2 & 3) == 0) s0 += a; else if ((c2 & 3) == 1) s1 += a;
                else if ((c2 & 3) == 2) s2 += a; else s3 += a;
                bb |= ((unsigned)(v < 0.f)) << c2;
                if (v == 0.f) {
                    int idx = atomicAdd(&g_xz_count, 1);
                    if (idx < 4096) g_xz_list[idx] = (n * C_ + w8 * 32 + c2) * PIX + pix;
                }
            }
            bits[w8] = bb;
        }
        uint4* dst = (uint4*)&g_xbits[((size_t)n * PIX + pix) * 8];
        dst[0] = make_uint4(bits[0], bits[1], bits[2], bits[3]);
        dst[1] = make_uint4(bits[4], bits[5], bits[6], bits[7]);
    }

    __shared__ float red[256];
    red[tid] = (s0 + s1) + (s2 + s3);
    __syncthreads();
    for (int st = 128; st > 0; st >>= 1) {
        if (tid < st) red[tid] += red[tid + st];
        __syncthreads();
    }
    if (tid == 0) atomicAdd(&g_asum[n], red[0]);
}

// ---------------- K2: pack w sign bits, per-tap popcounts, m[o] ----------------
__global__ void k_packw(const float* __restrict__ w) {
    int o = blockIdx.x;
    int tid = threadIdx.x;
    int j = tid >> 5, lane = tid & 31;
    int c = j * 32 + lane;

    float s = 0.f;
#pragma unroll
    for (int tap = 0; tap < 9; tap++) {
        float v = w[((size_t)(o * C_ + c)) * 9 + tap];
        s += fabsf(v);
        unsigned bal = __ballot_sync(0xffffffffu, v < 0.f);
        if (lane == 0) {
            g_wbits[o * 72 + tap * 8 + j] = bal;
            atomicAdd(&g_pw[o * 9 + tap], __popc(bal));
        }
        if (v == 0.f) {
            int idx = atomicAdd(&g_wz_count, 1);
            if (idx < 64) g_wz_list[idx] = (o * C_ + c) * 9 + tap;
        }
    }
    __shared__ float red[256];
    red[tid] = s;
    __syncthreads();
    for (int st = 128; st > 0; st >>= 1) {
        if (tid < st) red[tid] += red[tid + st];
        __syncthreads();
    }
    if (tid == 0) g_m[o] = red[0] / 2304.f;
}

// ---------------- K3: XNOR-popcount conv, 2 vertical pixels / thread ----------------
// block = (n, 8 output rows); 224 threads = 4 row-pairs x 56 cols; loops all 256 o.
// SMEM words: ws 18432 | pw 2304 | ms 256 | xt 10*58*9 = 5220  -> 104848 B
#define SM_PW  18432
#define SM_MS  (18432 + 2304)
#define SM_XT  (18432 + 2304 + 256)
#define CONV_SMEM ((18432 + 2304 + 256 + 10*58*9) * 4)

__global__ __launch_bounds__(224, 2) void k_conv(float* __restrict__ out) {
    extern __shared__ unsigned sm[];
    unsigned* ws = sm;
    int*      pw = (int*)(sm + SM_PW);
    float*    ms = (float*)(sm + SM_MS);
    unsigned* xt = sm + SM_XT;

    int b = blockIdx.x;
    int n = b & 31;
    int ohBase = (b >> 5) * 8;           // 7 row-groups of 8
    int tid = threadIdx.x;

    for (int i = tid; i < 4608; i += 224)
        ((uint4*)ws)[i] = ((const uint4*)g_wbits)[i];
    for (int i = tid; i < 2304; i += 224) pw[i] = g_pw[i];
    for (int i = tid; i < 256; i += 224) ms[i] = g_m[i];

    // x tile: 10 rows x 58 cols, pixel stride 9 words (bank-conflict-free)
    for (int u = tid; u < 10 * 58 * 2; u += 224) {
        int half = u & 1;
        int t = u >> 1;
        int col = t % 58;
        int rr = t / 58;
        int ih = ohBase - 1 + rr;
        int iw = col - 1;
        uint4 v = make_uint4(0u, 0u, 0u, 0u);
        if (ih >= 0 && ih < HW_ && iw >= 0 && iw < HW_)
            v = *(const uint4*)&g_xbits[((size_t)n * PIX + ih * HW_ + iw) * 8 + half * 4];
        unsigned* d = &xt[(rr * 58 + col) * 9 + half * 4];
        d[0] = v.x; d[1] = v.y; d[2] = v.z; d[3] = v.w;
    }
    __syncthreads();

    int rp = tid / 56, ow = tid % 56;
    int oh0 = ohBase + rp * 2;           // pixel0 row; pixel1 = oh0 + 1

    // 4 rows x 3 cols x 8 words window, shared by both pixels
    unsigned X[96];
#pragma unroll
    for (int rr = 0; rr < 4; rr++)
#pragma unroll
        for (int cc = 0; cc < 3; cc++) {
            const unsigned* p = &xt[((rp * 2 + rr) * 58 + ow + cc) * 9];
#pragma unroll
            for (int k = 0; k < 8; k++) X[(rr * 3 + cc) * 8 + k] = p[k];
        }

    // invalid-tap masks for padding
    unsigned bm0 = 0, bm1 = 0;
#pragma unroll
    for (int t = 0; t < 9; t++) {
        int kh = t / 3, kw = t % 3;
        bool ce = (kw == 0 && ow == 0) || (kw == 2 && ow == HW_ - 1);
        if (ce || (kh == 0 && oh0 == 0)          || (kh == 2 && oh0 == HW_ - 1))     bm0 |= 1u << t;
        if (ce || (kh == 0 && oh0 + 1 == 0)      || (kh == 2 && oh0 + 1 == HW_ - 1)) bm1 |= 1u << t;
    }

    float al = alpha_of(n);
    float* ob = out + (size_t)n * O_ * PIX + oh0 * HW_ + ow;

    for (int o = 0; o < O_; o++) {
        const uint4* wp = (const uint4*)&ws[o * 72];
        int a0 = 0, a1 = 0;
#pragma unroll
        for (int kh = 0; kh < 3; kh++)
#pragma unroll
            for (int kw = 0; kw < 3; kw++) {
                uint4 wa = wp[(kh * 3 + kw) * 2];
                uint4 wb = wp[(kh * 3 + kw) * 2 + 1];
                const unsigned* x0 = &X[(kh * 3 + kw) * 8];
                const unsigned* x1 = &X[((kh + 1) * 3 + kw) * 8];
                a0 += __popc(x0[0] ^ wa.x) + __popc(x0[1] ^ wa.y) +
                      __popc(x0[2] ^ wa.z) + __popc(x0[3] ^ wa.w) +
                      __popc(x0[4] ^ wb.x) + __popc(x0[5] ^ wb.y) +
                      __popc(x0[6] ^ wb.z) + __popc(x0[7] ^ wb.w);
                a1 += __popc(x1[0] ^ wa.x) + __popc(x1[1] ^ wa.y) +
                      __popc(x1[2] ^ wa.z) + __popc(x1[3] ^ wa.w) +
                      __popc(x1[4] ^ wb.x) + __popc(x1[5] ^ wb.y) +
                      __popc(x1[6] ^ wb.z) + __popc(x1[7] ^ wb.w);
            }
        int S0 = 2304 - 2 * a0;
        int S1 = 2304 - 2 * a1;
        if (bm0) {
            unsigned m2 = bm0;
            while (m2) { int t = __ffs(m2) - 1; m2 &= m2 - 1; S0 -= 256 - 2 * pw[o * 9 + t]; }
        }
        if (bm1) {
            unsigned m2 = bm1;
            while (m2) { int t = __ffs(m2) - 1; m2 &= m2 - 1; S1 -= 256 - 2 * pw[o * 9 + t]; }
        }
        float f = al * ms[o];
        ob[(size_t)o * PIX]        = f * (float)S0;
        ob[(size_t)o * PIX + HW_]  = f * (float)S1;
    }
}

// ---------------- K4: exact correction for x==0 elements ----------------
__global__ void k_xzero(float* __restrict__ out) {
    int zc = g_xz_count;
    if (zc > 4096) zc = 4096;
    long total = (long)zc * 2304;
    for (long i = (long)blockIdx.x * blockDim.x + threadIdx.x; i < total;
         i += (long)gridDim.x * blockDim.x) {
        int z = (int)(i / 2304);
        int q = (int)(i % 2304);
        int o = q / 9, tap = q % 9;
        int li = g_xz_list[z];
        int pix = li % PIX;
        int ch = (li / PIX) & 255;
        int n = li / (PIX * C_);
        int h = pix / HW_, wv = pix % HW_;
        int kh = tap / 3, kw = tap % 3;
        int oh = h + 1 - kh, ow = wv + 1 - kw;
        if ((unsigned)oh < HW_ && (unsigned)ow < HW_) {
            unsigned bit = (g_wbits[o * 72 + tap * 8 + (ch >> 5)] >> (ch & 31)) & 1u;
            float bw = bit ? -1.f : 1.f;   // encoded product was (+1)*bw; truth is 0
            atomicAdd(&out[((size_t)(n * O_ + o)) * PIX + oh * HW_ + ow],
                      -bw * alpha_of(n) * g_m[o]);
        }
    }
}

// ---------------- K5: exact correction for w==0 elements ----------------
__global__ void k_wzero(const float* __restrict__ x, float* __restrict__ out) {
    int zc = g_wz_count;
    if (zc > 64) zc = 64;
    long total = (long)zc * N_ * PIX;
    for (long i = (long)blockIdx.x * blockDim.x + threadIdx.x; i < total;
         i += (long)gridDim.x * blockDim.x) {
        int z = (int)(i / ((long)N_ * PIX));
        int rte = (int)(i % ((long)N_ * PIX));
        int n = rte / PIX, pix = rte % PIX;
        int oh = pix / HW_, ow = pix % HW_;
        int li = g_wz_list[z];
        int tap = li % 9;
        int ch = (li / 9) & 255;
        int o = li / (9 * C_);
        int kh = tap / 3, kw = tap % 3;
        int ih = oh - 1 + kh, iw = ow - 1 + kw;
        if ((unsigned)ih < HW_ && (unsigned)iw < HW_) {
            float xv = x[((size_t)(n * C_ + ch)) * PIX + ih * HW_ + iw];
            if (xv != 0.f) {               // x==0 already fixed by k_xzero
                float bx = (xv < 0.f) ? -1.f : 1.f;
                atomicAdd(&out[((size_t)(n * O_ + o)) * PIX + pix],
                          -bx * alpha_of(n) * g_m[o]);
            }
        }
    }
}

// ---------------- launch ----------------
extern "C" void kernel_launch(void* const* d_in, const int* in_sizes, int n_in,
                              void* d_out, int out_size) {
    const float* x = (const float*)d_in[0];
    const float* w = (const float*)d_in[1];
    float* out = (float*)d_out;

    cudaFuncSetAttribute(k_conv, cudaFuncAttributeMaxDynamicSharedMemorySize, CONV_SMEM);

    k_zero<<<9, 256>>>();
    k_packx<<<416, 256>>>(x);
    k_packw<<<256, 256>>>(w);
    k_conv<<<224, 224, CONV_SMEM>>>(out);
    k_xzero<<<64, 256>>>(out);
    k_wzero<<<128, 256>>>(x, out);
}

// round 4
// speedup vs baseline: 1.1600x; 1.1600x over previous
#include <cuda_runtime.h>
#include <cstdint>

#define N_   32
#define C_   256
#define O_   256
#define HW_  56
#define PIX  3136          // 56*56
#define CNTS 802816.0f     // 256*56*56 per-sample element count
#define EPSF 1e-5f

// ---------------- device scratch (no allocations allowed) ----------------
__device__ float    g_asum[N_];
__device__ float    g_m[O_];
__device__ __align__(16) unsigned g_wbits[O_ * 72];      // [o][tap][word] 9 taps * 8 words
__device__ int      g_pw[O_ * 9];                        // popc of wbits per (o,tap)
__device__ __align__(16) unsigned g_xbits[(size_t)N_ * PIX * 8]; // [n][pix][word]
__device__ int      g_xz_count;
__device__ int      g_wz_count;
__device__ int      g_xz_list[4096];                     // linear idx into x
__device__ int      g_wz_list[64];                       // linear idx into w

__device__ __forceinline__ float alpha_of(int n) {
    return fmaxf(2.f * g_asum[n] / CNTS, EPSF);
}

// ---------------- K0: zero counters/accumulators ----------------
__global__ void k_zero() {
    int t = blockIdx.x * blockDim.x + threadIdx.x;
    if (t < N_) g_asum[t] = 0.f;
    if (t < O_ * 9) g_pw[t] = 0;
    if (t == 0) { g_xz_count = 0; g_wz_count = 0; }
}

// ---------------- K1: pack x sign bits + accumulate sum|x| ----------------
// thread <-> pixel; loops all 256 channels; dense uint4 writes
__global__ void k_packx(const float* __restrict__ x) {
    int b    = blockIdx.x;
    int n    = b & 31;
    int pix  = (b >> 5) * 256 + threadIdx.x;
    int tid  = threadIdx.x;

    unsigned bits[8] = {0,0,0,0,0,0,0,0};
    float s0 = 0.f, s1 = 0.f, s2 = 0.f, s3 = 0.f;

    if (pix < PIX) {
        const float* base = x + (size_t)n * C_ * PIX + pix;
#pragma unroll
        for (int w8 = 0; w8 < 8; w8++) {
            unsigned bb = 0;
#pragma unroll
            for (int c2 = 0; c2 < 32; c2++) {
                float v = base[(size_t)(w8 * 32 + c2) * PIX];
                float a = fabsf(v);
                if ((c2 & 3) == 0) s0 += a; else if ((c2 & 3) == 1) s1 += a;
                else if ((c2 & 3) == 2) s2 += a; else s3 += a;
                bb |= ((unsigned)(v < 0.f)) << c2;
                if (v == 0.f) {
                    int idx = atomicAdd(&g_xz_count, 1);
                    if (idx < 4096) g_xz_list[idx] = (n * C_ + w8 * 32 + c2) * PIX + pix;
                }
            }
            bits[w8] = bb;
        }
        uint4* dst = (uint4*)&g_xbits[((size_t)n * PIX + pix) * 8];
        dst[0] = make_uint4(bits[0], bits[1], bits[2], bits[3]);
        dst[1] = make_uint4(bits[4], bits[5], bits[6], bits[7]);
    }

    __shared__ float red[256];
    red[tid] = (s0 + s1) + (s2 + s3);
    __syncthreads();
    for (int st = 128; st > 0; st >>= 1) {
        if (tid < st) red[tid] += red[tid + st];
        __syncthreads();
    }
    if (tid == 0) atomicAdd(&g_asum[n], red[0]);
}

// ---------------- K2: pack w sign bits, per-tap popcounts, m[o] ----------------
__global__ void k_packw(const float* __restrict__ w) {
    int o = blockIdx.x;
    int tid = threadIdx.x;
    int j = tid >> 5, lane = tid & 31;
    int c = j * 32 + lane;

    float s = 0.f;
#pragma unroll
    for (int tap = 0; tap < 9; tap++) {
        float v = w[((size_t)(o * C_ + c)) * 9 + tap];
        s += fabsf(v);
        unsigned bal = __ballot_sync(0xffffffffu, v < 0.f);
        if (lane == 0) {
            g_wbits[o * 72 + tap * 8 + j] = bal;
            atomicAdd(&g_pw[o * 9 + tap], __popc(bal));
        }
        if (v == 0.f) {
            int idx = atomicAdd(&g_wz_count, 1);
            if (idx < 64) g_wz_list[idx] = (o * C_ + c) * 9 + tap;
        }
    }
    __shared__ float red[256];
    red[tid] = s;
    __syncthreads();
    for (int st = 128; st > 0; st >>= 1) {
        if (tid < st) red[tid] += red[tid + st];
        __syncthreads();
    }
    if (tid == 0) g_m[o] = red[0] / 2304.f;
}

// ---------------- K3: XNOR-popcount conv, 1 pixel / thread ----------------
// block = (n, 4 output rows); 224 threads = 4 rows x 56 cols; loops all 256 o.
// SMEM = x tile only: 6 rows x 58 cols x 9-word stride = 12528 B -> 3 blocks/SM
#define CONV_SMEM (6 * 58 * 9 * 4)

__global__ __launch_bounds__(224, 3) void k_conv(float* __restrict__ out) {
    extern __shared__ unsigned xt[];

    int b = blockIdx.x;
    int n = b & 31;
    int ohBase = (b >> 5) * 4;           // 14 row-groups of 4
    int tid = threadIdx.x;

    // x tile: 6 rows x 58 cols, pixel stride 9 words (bank-conflict-free)
    for (int u = tid; u < 6 * 58 * 2; u += 224) {
        int half = u & 1;
        int t = u >> 1;
        int col = t % 58;
        int rr = t / 58;
        int ih = ohBase - 1 + rr;
        int iw = col - 1;
        uint4 v = make_uint4(0u, 0u, 0u, 0u);
        if (ih >= 0 && ih < HW_ && iw >= 0 && iw < HW_)
            v = *(const uint4*)&g_xbits[((size_t)n * PIX + ih * HW_ + iw) * 8 + half * 4];
        unsigned* d = &xt[(rr * 58 + col) * 9 + half * 4];
        d[0] = v.x; d[1] = v.y; d[2] = v.z; d[3] = v.w;
    }
    __syncthreads();

    int r = tid / 56, ow = tid % 56;
    int oh = ohBase + r;

    // 3x3x8-word x window in registers, reused across all 256 o
    unsigned X[72];
#pragma unroll
    for (int kh = 0; kh < 3; kh++)
#pragma unroll
        for (int kw = 0; kw < 3; kw++) {
            const unsigned* p = &xt[((r + kh) * 58 + ow + kw) * 9];
#pragma unroll
            for (int k = 0; k < 8; k++) X[(kh * 3 + kw) * 8 + k] = p[k];
        }

    // invalid-tap mask for padding
    unsigned bm = 0;
#pragma unroll
    for (int t = 0; t < 9; t++) {
        int kh = t / 3, kw = t % 3;
        bool inv = (kh == 0 && oh == 0) || (kh == 2 && oh == HW_ - 1) ||
                   (kw == 0 && ow == 0) || (kw == 2 && ow == HW_ - 1);
        if (inv) bm |= 1u << t;
    }

    float al = alpha_of(n);
    float* ob = out + (size_t)n * O_ * PIX + oh * HW_ + ow;
    const uint4* wg = (const uint4*)g_wbits;

    for (int o = 0; o < O_; o++) {
        const uint4* wp = wg + o * 18;
        int acc = 0;
#pragma unroll
        for (int t = 0; t < 9; t++) {
            uint4 wa = __ldg(wp + t * 2);
            uint4 wb = __ldg(wp + t * 2 + 1);
            const unsigned* Xp = &X[t * 8];
            acc += __popc(Xp[0] ^ wa.x) + __popc(Xp[1] ^ wa.y) +
                   __popc(Xp[2] ^ wa.z) + __popc(Xp[3] ^ wa.w) +
                   __popc(Xp[4] ^ wb.x) + __popc(Xp[5] ^ wb.y) +
                   __popc(Xp[6] ^ wb.z) + __popc(Xp[7] ^ wb.w);
        }
        int S = 2304 - 2 * acc;
        if (bm) {
            unsigned m2 = bm;
            while (m2) {
                int t = __ffs(m2) - 1;
                m2 &= m2 - 1;
                S -= 256 - 2 * __ldg(&g_pw[o * 9 + t]);
            }
        }
        ob[(size_t)o * PIX] = al * __ldg(&g_m[o]) * (float)S;
    }
}

// ---------------- K4: exact correction for x==0 elements ----------------
__global__ void k_xzero(float* __restrict__ out) {
    int zc = g_xz_count;
    if (zc > 4096) zc = 4096;
    long total = (long)zc * 2304;
    for (long i = (long)blockIdx.x * blockDim.x + threadIdx.x; i < total;
         i += (long)gridDim.x * blockDim.x) {
        int z = (int)(i / 2304);
        int q = (int)(i % 2304);
        int o = q / 9, tap = q % 9;
        int li = g_xz_list[z];
        int pix = li % PIX;
        int ch = (li / PIX) & 255;
        int n = li / (PIX * C_);
        int h = pix / HW_, wv = pix % HW_;
        int kh = tap / 3, kw = tap % 3;
        int oh = h + 1 - kh, ow = wv + 1 - kw;
        if ((unsigned)oh < HW_ && (unsigned)ow < HW_) {
            unsigned bit = (g_wbits[o * 72 + tap * 8 + (ch >> 5)] >> (ch & 31)) & 1u;
            float bw = bit ? -1.f : 1.f;   // encoded product was (+1)*bw; truth is 0
            atomicAdd(&out[((size_t)(n * O_ + o)) * PIX + oh * HW_ + ow],
                      -bw * alpha_of(n) * g_m[o]);
        }
    }
}

// ---------------- K5: exact correction for w==0 elements ----------------
__global__ void k_wzero(const float* __restrict__ x, float* __restrict__ out) {
    int zc = g_wz_count;
    if (zc > 64) zc = 64;
    long total = (long)zc * N_ * PIX;
    for (long i = (long)blockIdx.x * blockDim.x + threadIdx.x; i < total;
         i += (long)gridDim.x * blockDim.x) {
        int z = (int)(i / ((long)N_ * PIX));
        int rte = (int)(i % ((long)N_ * PIX));
        int n = rte / PIX, pix = rte % PIX;
        int oh = pix / HW_, ow = pix % HW_;
        int li = g_wz_list[z];
        int tap = li % 9;
        int ch = (li / 9) & 255;
        int o = li / (9 * C_);
        int kh = tap / 3, kw = tap % 3;
        int ih = oh - 1 + kh, iw = ow - 1 + kw;
        if ((unsigned)ih < HW_ && (unsigned)iw < HW_) {
            float xv = x[((size_t)(n * C_ + ch)) * PIX + ih * HW_ + iw];
            if (xv != 0.f) {               // x==0 already fixed by k_xzero
                float bx = (xv < 0.f) ? -1.f : 1.f;
                atomicAdd(&out[((size_t)(n * O_ + o)) * PIX + pix],
                          -bx * alpha_of(n) * g_m[o]);
            }
        }
    }
}

// ---------------- launch ----------------
extern "C" void kernel_launch(void* const* d_in, const int* in_sizes, int n_in,
                              void* d_out, int out_size) {
    const float* x = (const float*)d_in[0];
    const float* w = (const float*)d_in[1];
    float* out = (float*)d_out;

    k_zero<<<9, 256>>>();
    k_packx<<<416, 256>>>(x);
    k_packw<<<256, 256>>>(w);
    k_conv<<<448, 224, CONV_SMEM>>>(out);
    k_xzero<<<64, 256>>>(out);
    k_wzero<<<128, 256>>>(x, out);
}

// round 6
// speedup vs baseline: 1.3556x; 1.1686x over previous
#include <cuda_runtime.h>
#include <cstdint>

#define N_   32
#define C_   256
#define O_   256
#define HW_  56
#define PIX  3136
#define CNTS 802816.0f
#define EPSF 1e-5f

// ---------------- device scratch ----------------
__device__ float    g_asum[N_];
__device__ float    g_m[O_];
__device__ __align__(16) unsigned g_wt[9 * O_ * 8];       // [tap][o][word]
__device__ int      g_pw[O_ * 9];                          // popc per (o,tap)
__device__ __align__(16) unsigned g_xbits[(size_t)N_ * PIX * 8]; // [n][pix][word]
__device__ int      g_xz_count;
__device__ int      g_wz_count;
__device__ int      g_xz_list[4096];
__device__ int      g_wz_list[64];

__device__ __forceinline__ float alpha_of(int n) {
    return fmaxf(2.f * g_asum[n] / CNTS, EPSF);
}

// ---------------- K0 ----------------
__global__ void k_zero() {
    int t = blockIdx.x * blockDim.x + threadIdx.x;
    if (t < N_) g_asum[t] = 0.f;
    if (t < O_ * 9) g_pw[t] = 0;
    if (t == 0) { g_xz_count = 0; g_wz_count = 0; }
}

// ---------------- K1: pack x ----------------
__global__ void k_packx(const float* __restrict__ x) {
    int b   = blockIdx.x;
    int n   = b & 31;
    int pix = (b >> 5) * 256 + threadIdx.x;
    int tid = threadIdx.x;

    unsigned bits[8] = {0,0,0,0,0,0,0,0};
    float s0 = 0.f, s1 = 0.f, s2 = 0.f, s3 = 0.f;

    if (pix < PIX) {
        const float* base = x + (size_t)n * C_ * PIX + pix;
#pragma unroll
        for (int w8 = 0; w8 < 8; w8++) {
            unsigned bb = 0;
#pragma unroll
            for (int c2 = 0; c2 < 32; c2++) {
                float v = base[(size_t)(w8 * 32 + c2) * PIX];
                float a = fabsf(v);
                if ((c2 & 3) == 0) s0 += a; else if ((c2 & 3) == 1) s1 += a;
                else if ((c2 & 3) == 2) s2 += a; else s3 += a;
                bb |= ((unsigned)(v < 0.f)) << c2;
                if (v == 0.f) {
                    int idx = atomicAdd(&g_xz_count, 1);
                    if (idx < 4096) g_xz_list[idx] = (n * C_ + w8 * 32 + c2) * PIX + pix;
                }
            }
            bits[w8] = bb;
        }
        uint4* dst = (uint4*)&g_xbits[((size_t)n * PIX + pix) * 8];
        dst[0] = make_uint4(bits[0], bits[1], bits[2], bits[3]);
        dst[1] = make_uint4(bits[4], bits[5], bits[6], bits[7]);
    }

    __shared__ float red[256];
    red[tid] = (s0 + s1) + (s2 + s3);
    __syncthreads();
    for (int st = 128; st > 0; st >>= 1) {
        if (tid < st) red[tid] += red[tid + st];
        __syncthreads();
    }
    if (tid == 0) atomicAdd(&g_asum[n], red[0]);
}

// ---------------- K2: pack w  ([tap][o][word] layout) ----------------
__global__ void k_packw(const float* __restrict__ w) {
    int o = blockIdx.x;
    int tid = threadIdx.x;
    int j = tid >> 5, lane = tid & 31;
    int c = j * 32 + lane;

    float s = 0.f;
#pragma unroll
    for (int tap = 0; tap < 9; tap++) {
        float v = w[((size_t)(o * C_ + c)) * 9 + tap];
        s += fabsf(v);
        unsigned bal = __ballot_sync(0xffffffffu, v < 0.f);
        if (lane == 0) {
            g_wt[((size_t)tap * O_ + o) * 8 + j] = bal;
            atomicAdd(&g_pw[o * 9 + tap], __popc(bal));
        }
        if (v == 0.f) {
            int idx = atomicAdd(&g_wz_count, 1);
            if (idx < 64) g_wz_list[idx] = (o * C_ + c) * 9 + tap;
        }
    }
    __shared__ float red[256];
    red[tid] = s;
    __syncthreads();
    for (int st = 128; st > 0; st >>= 1) {
        if (tid < st) red[tid] += red[tid + st];
        __syncthreads();
    }
    if (tid == 0) g_m[o] = red[0] / 2304.f;
}

// ---------------- K3: XNOR-popcount conv, 16-o groups, X streamed from SMEM ----
// grid = 32 n * 14 rowgroups * 2 o-halves = 896 blocks, 224 threads, 5 blocks/SM
__global__ __launch_bounds__(224, 5) void k_conv(float* __restrict__ out) {
    __shared__ unsigned xt[6 * 58 * 9];

    int b = blockIdx.x;
    int n = b & 31;
    int t2 = b >> 5;                  // 0..27
    int ohBase = (t2 >> 1) * 4;
    int oBase  = (t2 & 1) * 128;
    int tid = threadIdx.x;

    // x tile: 6 rows x 58 cols, pixel stride 9 words (conflict-free)
    for (int u = tid; u < 6 * 58 * 2; u += 224) {
        int half = u & 1;
        int t = u >> 1;
        int col = t % 58;
        int rr = t / 58;
        int ih = ohBase - 1 + rr;
        int iw = col - 1;
        uint4 v = make_uint4(0u, 0u, 0u, 0u);
        if (ih >= 0 && ih < HW_ && iw >= 0 && iw < HW_)
            v = *(const uint4*)&g_xbits[((size_t)n * PIX + ih * HW_ + iw) * 8 + half * 4];
        unsigned* d = &xt[(rr * 58 + col) * 9 + half * 4];
        d[0] = v.x; d[1] = v.y; d[2] = v.z; d[3] = v.w;
    }
    __syncthreads();

    int r = tid / 56, ow = tid % 56;
    int oh = ohBase + r;
    const unsigned* xrow = &xt[(r * 58 + ow) * 9];

    unsigned bm = 0;
#pragma unroll
    for (int t = 0; t < 9; t++) {
        int kh = t / 3, kw = t % 3;
        bool inv = (kh == 0 && oh == 0) || (kh == 2 && oh == HW_ - 1) ||
                   (kw == 0 && ow == 0) || (kw == 2 && ow == HW_ - 1);
        if (inv) bm |= 1u << t;
    }

    float al = alpha_of(n);
    float* ob = out + ((size_t)n * O_ + oBase) * PIX + oh * HW_ + ow;

    for (int og = 0; og < 8; og++) {
        int o0 = oBase + og * 16;
        int acc[16];
#pragma unroll
        for (int j = 0; j < 16; j++) acc[j] = 0;

#pragma unroll 1
        for (int kh = 0; kh < 3; kh++) {
#pragma unroll 1
            for (int kw = 0; kw < 3; kw++) {
                const unsigned* xp = xrow + (kh * 58 + kw) * 9;
                unsigned x0 = xp[0], x1 = xp[1], x2 = xp[2], x3 = xp[3];
                unsigned x4 = xp[4], x5 = xp[5], x6 = xp[6], x7 = xp[7];
                int t = kh * 3 + kw;
                const uint4* wp = (const uint4*)&g_wt[((size_t)t * O_ + o0) * 8];
#pragma unroll
                for (int j = 0; j < 16; j++) {
                    uint4 wa = __ldg(wp + j * 2);
                    uint4 wb = __ldg(wp + j * 2 + 1);
                    acc[j] += __popc(x0 ^ wa.x) + __popc(x1 ^ wa.y) +
                              __popc(x2 ^ wa.z) + __popc(x3 ^ wa.w) +
                              __popc(x4 ^ wb.x) + __popc(x5 ^ wb.y) +
                              __popc(x6 ^ wb.z) + __popc(x7 ^ wb.w);
                }
            }
        }

#pragma unroll
        for (int j = 0; j < 16; j++) {
            int S = 2304 - 2 * acc[j];
            if (bm) {
                unsigned m2 = bm;
                while (m2) {
                    int t = __ffs(m2) - 1;
                    m2 &= m2 - 1;
                    S -= 256 - 2 * __ldg(&g_pw[(o0 + j) * 9 + t]);
                }
            }
            ob[(size_t)(og * 16 + j) * PIX] = al * __ldg(&g_m[o0 + j]) * (float)S;
        }
    }
}

// ---------------- K4: exact correction for x==0 ----------------
__global__ void k_xzero(float* __restrict__ out) {
    int zc = g_xz_count;
    if (zc > 4096) zc = 4096;
    long total = (long)zc * 2304;
    for (long i = (long)blockIdx.x * blockDim.x + threadIdx.x; i < total;
         i += (long)gridDim.x * blockDim.x) {
        int z = (int)(i / 2304);
        int q = (int)(i % 2304);
        int o = q / 9, tap = q % 9;
        int li = g_xz_list[z];
        int pix = li % PIX;
        int ch = (li / PIX) & 255;
        int n = li / (PIX * C_);
        int h = pix / HW_, wv = pix % HW_;
        int kh = tap / 3, kw = tap % 3;
        int oh = h + 1 - kh, ow = wv + 1 - kw;
        if ((unsigned)oh < HW_ && (unsigned)ow < HW_) {
            unsigned bit = (g_wt[((size_t)tap * O_ + o) * 8 + (ch >> 5)] >> (ch & 31)) & 1u;
            float bw = bit ? -1.f : 1.f;
            atomicAdd(&out[((size_t)(n * O_ + o)) * PIX + oh * HW_ + ow],
                      -bw * alpha_of(n) * g_m[o]);
        }
    }
}

// ---------------- K5: exact correction for w==0 ----------------
__global__ void k_wzero(const float* __restrict__ x, float* __restrict__ out) {
    int zc = g_wz_count;
    if (zc > 64) zc = 64;
    long total = (long)zc * N_ * PIX;
    for (long i = (long)blockIdx.x * blockDim.x + threadIdx.x; i < total;
         i += (long)gridDim.x * blockDim.x) {
        int z = (int)(i / ((long)N_ * PIX));
        int rte = (int)(i % ((long)N_ * PIX));
        int n = rte / PIX, pix = rte % PIX;
        int oh = pix / HW_, ow = pix % HW_;
        int li = g_wz_list[z];
        int tap = li % 9;
        int ch = (li / 9) & 255;
        int o = li / (9 * C_);
        int kh = tap / 3, kw = tap % 3;
        int ih = oh - 1 + kh, iw = ow - 1 + kw;
        if ((unsigned)ih < HW_ && (unsigned)iw < HW_) {
            float xv = x[((size_t)(n * C_ + ch)) * PIX + ih * HW_ + iw];
            if (xv != 0.f) {
                float bx = (xv < 0.f) ? -1.f : 1.f;
                atomicAdd(&out[((size_t)(n * O_ + o)) * PIX + pix],
                          -bx * alpha_of(n) * g_m[o]);
            }
        }
    }
}

// ---------------- launch ----------------
extern "C" void kernel_launch(void* const* d_in, const int* in_sizes, int n_in,
                              void* d_out, int out_size) {
    const float* x = (const float*)d_in[0];
    const float* w = (const float*)d_in[1];
    float* out = (float*)d_out;

    k_zero<<<9, 256>>>();
    k_packx<<<416, 256>>>(x);
    k_packw<<<256, 256>>>(w);
    k_conv<<<896, 224>>>(out);
    k_xzero<<<64, 256>>>(out);
    k_wzero<<<128, 256>>>(x, out);
}